// round 11
// baseline (speedup 1.0000x reference)
#include <cuda_runtime.h>

// out[bh][q*96+v] = K[bh,3,q] * u[v];  u = (scale*q3 @ V) @ W3
// 192 blocks, 576 threads = 24 col4-groups x 24 k-groups.
// R9 layout (best measured) with: float4 q load, scale folded into q.

#define SD    96
#define C4    24      // float4 columns per row
#define KG    24      // k groups
#define KSPAN 4       // 96 / KG
#define NT    (C4 * KG)   // 576

__global__ __launch_bounds__(NT, 2) void mma73_kernel(
    const float* __restrict__ Q,
    const float* __restrict__ K,
    const float* __restrict__ V,
    const float* __restrict__ DW,
    const int*   __restrict__ uidx_p,
    float* __restrict__ out)
{
    const int tid = threadIdx.x;
    const int c4  = tid % C4;     // 0..23
    const int grp = tid / C4;     // 0..23
    const int bh  = blockIdx.x;   // 0..191

    __shared__ float t_s[SD];
    __shared__ __align__(16) float u_s[SD];
    __shared__ __align__(16) float4 part4[KG][C4];

    const int uidx = __ldg(uidx_p);

    const float4* __restrict__ Vb4 = (const float4*)(V + (size_t)bh * SD * SD);
    const float4* __restrict__ W4  = (const float4*)(DW + (size_t)uidx * SD * SD);
    const size_t qk_base = ((size_t)bh * SD + 3) * SD;

    // ---- front-batched independent loads ----
    float4 v_r[KSPAN], w_r[KSPAN];
    float  k_r[KSPAN];
    #pragma unroll
    for (int j = 0; j < KSPAN; ++j)
        v_r[j] = Vb4[(grp * KSPAN + j) * C4 + c4];
    #pragma unroll
    for (int j = 0; j < KSPAN; ++j)
        w_r[j] = W4[(grp * KSPAN + j) * C4 + c4];
    // q chunk for this k-group as one vector load (scale folded in below)
    float4 q4 = __ldg((const float4*)(Q + qk_base) + grp);
    #pragma unroll
    for (int j = 0; j < KSPAN; ++j)
        k_r[j] = __ldg(K + qk_base + j * KG + grp);      // rows for phase 3

    const float scale = 0.10206207261596575f;   // 1/sqrt(96)
    float q_r[KSPAN];
    q_r[0] = q4.x * scale;  q_r[1] = q4.y * scale;
    q_r[2] = q4.z * scale;  q_r[3] = q4.w * scale;

    // ---- phase 1 partials (sync-free start): 16 FMA ----
    {
        float4 a;
        a.x = q_r[0] * v_r[0].x;  a.y = q_r[0] * v_r[0].y;
        a.z = q_r[0] * v_r[0].z;  a.w = q_r[0] * v_r[0].w;
        #pragma unroll
        for (int j = 1; j < KSPAN; ++j) {
            a.x += q_r[j] * v_r[j].x;  a.y += q_r[j] * v_r[j].y;
            a.z += q_r[j] * v_r[j].z;  a.w += q_r[j] * v_r[j].w;
        }
        part4[grp][c4] = a;
    }
    __syncthreads();

    // ---- t reduce: 96 threads, 24 adds each ----
    if (tid < SD) {
        const float* p = (const float*)part4;   // [KG][SD]
        float s = p[tid];
        #pragma unroll
        for (int g = 1; g < KG; ++g) s += p[g * SD + tid];
        t_s[tid] = s;
    }
    __syncthreads();

    // ---- phase 2 partials: 16 FMA ----
    {
        const float t0 = t_s[grp * KSPAN + 0];
        const float t1 = t_s[grp * KSPAN + 1];
        const float t2 = t_s[grp * KSPAN + 2];
        const float t3 = t_s[grp * KSPAN + 3];
        float4 a;
        a.x = t0 * w_r[0].x;  a.y = t0 * w_r[0].y;
        a.z = t0 * w_r[0].z;  a.w = t0 * w_r[0].w;
        a.x += t1 * w_r[1].x;  a.y += t1 * w_r[1].y;
        a.z += t1 * w_r[1].z;  a.w += t1 * w_r[1].w;
        a.x += t2 * w_r[2].x;  a.y += t2 * w_r[2].y;
        a.z += t2 * w_r[2].z;  a.w += t2 * w_r[2].w;
        a.x += t3 * w_r[3].x;  a.y += t3 * w_r[3].y;
        a.z += t3 * w_r[3].z;  a.w += t3 * w_r[3].w;
        part4[grp][c4] = a;
    }
    __syncthreads();

    // ---- u reduce: 96 threads (scale already folded) ----
    if (tid < SD) {
        const float* p = (const float*)part4;
        float s = p[tid];
        #pragma unroll
        for (int g = 1; g < KG; ++g) s += p[g * SD + tid];
        u_s[tid] = s;
    }
    __syncthreads();

    // ---- phase 3: outer product, 4 STG.128 ----
    float4* __restrict__ O4 = (float4*)(out + (size_t)bh * SD * SD);
    const float4 u4 = ((const float4*)u_s)[c4];
    #pragma unroll
    for (int r = 0; r < KSPAN; ++r) {
        const float kq = k_r[r];
        float4 o;
        o.x = kq * u4.x;  o.y = kq * u4.y;
        o.z = kq * u4.z;  o.w = kq * u4.w;
        O4[(r * KG + grp) * C4 + c4] = o;
    }
}

extern "C" void kernel_launch(void* const* d_in, const int* in_sizes, int n_in,
                              void* d_out, int out_size)
{
    const float* Q  = (const float*)d_in[0];
    const float* K  = (const float*)d_in[1];
    const float* V  = (const float*)d_in[2];
    const float* DW = (const float*)d_in[3];
    const int* uidx = (const int*)d_in[4];
    float* out      = (float*)d_out;

    mma73_kernel<<<192, NT>>>(Q, K, V, DW, uidx, out);
}

// round 12
// speedup vs baseline: 1.0853x; 1.0853x over previous
#include <cuda_runtime.h>

// out[bh][q*96+v] = K[bh,3,q] * u[v];  u = (scale*q3 @ V) @ W3
// 192 blocks, 576 threads = 24 col4-groups x 24 k-groups.
// R11 base + split-level reductions: 192 threads sum 12 partials each into
// two half-sums; consumers fold the final add (no extra barriers).

#define SD    96
#define C4    24      // float4 columns per row
#define KG    24      // k groups
#define KSPAN 4       // 96 / KG
#define HG    12      // KG/2 partials per reduce half
#define NT    (C4 * KG)   // 576

__global__ __launch_bounds__(NT, 2) void mma73_kernel(
    const float* __restrict__ Q,
    const float* __restrict__ K,
    const float* __restrict__ V,
    const float* __restrict__ DW,
    const int*   __restrict__ uidx_p,
    float* __restrict__ out)
{
    const int tid = threadIdx.x;
    const int c4  = tid % C4;     // 0..23
    const int grp = tid / C4;     // 0..23
    const int bh  = blockIdx.x;   // 0..191

    __shared__ float t2_s[2][SD];
    __shared__ __align__(16) float u2_s[2][SD];
    __shared__ __align__(16) float4 part4[KG][C4];

    const int uidx = __ldg(uidx_p);

    const float4* __restrict__ Vb4 = (const float4*)(V + (size_t)bh * SD * SD);
    const float4* __restrict__ W4  = (const float4*)(DW + (size_t)uidx * SD * SD);
    const size_t qk_base = ((size_t)bh * SD + 3) * SD;

    // ---- front-batched independent loads ----
    float4 v_r[KSPAN], w_r[KSPAN];
    float  k_r[KSPAN];
    #pragma unroll
    for (int j = 0; j < KSPAN; ++j)
        v_r[j] = Vb4[(grp * KSPAN + j) * C4 + c4];
    #pragma unroll
    for (int j = 0; j < KSPAN; ++j)
        w_r[j] = W4[(grp * KSPAN + j) * C4 + c4];
    float4 q4 = __ldg((const float4*)(Q + qk_base) + grp);  // q chunk, one LDG.128
    #pragma unroll
    for (int j = 0; j < KSPAN; ++j)
        k_r[j] = __ldg(K + qk_base + j * KG + grp);         // rows for phase 3

    const float scale = 0.10206207261596575f;   // 1/sqrt(96)
    float q_r[KSPAN];
    q_r[0] = q4.x * scale;  q_r[1] = q4.y * scale;
    q_r[2] = q4.z * scale;  q_r[3] = q4.w * scale;

    // ---- phase 1 partials (sync-free start): 16 FMA ----
    {
        float4 a;
        a.x = q_r[0] * v_r[0].x;  a.y = q_r[0] * v_r[0].y;
        a.z = q_r[0] * v_r[0].z;  a.w = q_r[0] * v_r[0].w;
        #pragma unroll
        for (int j = 1; j < KSPAN; ++j) {
            a.x += q_r[j] * v_r[j].x;  a.y += q_r[j] * v_r[j].y;
            a.z += q_r[j] * v_r[j].z;  a.w += q_r[j] * v_r[j].w;
        }
        part4[grp][c4] = a;
    }
    __syncthreads();

    // ---- t half-reduce: 192 threads, 12 adds each ----
    if (tid < 2 * SD) {
        const int hh = tid / SD, i = tid % SD;
        const float* p = (const float*)part4 + hh * HG * SD;   // [HG][SD] slice
        float s = p[i];
        #pragma unroll
        for (int g = 1; g < HG; ++g) s += p[g * SD + i];
        t2_s[hh][i] = s;
    }
    __syncthreads();

    // ---- phase 2 partials: combine halves inline, 16 FMA ----
    {
        const int i0 = grp * KSPAN;
        const float t0 = t2_s[0][i0 + 0] + t2_s[1][i0 + 0];
        const float t1 = t2_s[0][i0 + 1] + t2_s[1][i0 + 1];
        const float t2 = t2_s[0][i0 + 2] + t2_s[1][i0 + 2];
        const float t3 = t2_s[0][i0 + 3] + t2_s[1][i0 + 3];
        float4 a;
        a.x = t0 * w_r[0].x;  a.y = t0 * w_r[0].y;
        a.z = t0 * w_r[0].z;  a.w = t0 * w_r[0].w;
        a.x += t1 * w_r[1].x;  a.y += t1 * w_r[1].y;
        a.z += t1 * w_r[1].z;  a.w += t1 * w_r[1].w;
        a.x += t2 * w_r[2].x;  a.y += t2 * w_r[2].y;
        a.z += t2 * w_r[2].z;  a.w += t2 * w_r[2].w;
        a.x += t3 * w_r[3].x;  a.y += t3 * w_r[3].y;
        a.z += t3 * w_r[3].z;  a.w += t3 * w_r[3].w;
        part4[grp][c4] = a;
    }
    __syncthreads();

    // ---- u half-reduce: 192 threads, 12 adds each ----
    if (tid < 2 * SD) {
        const int hh = tid / SD, i = tid % SD;
        const float* p = (const float*)part4 + hh * HG * SD;
        float s = p[i];
        #pragma unroll
        for (int g = 1; g < HG; ++g) s += p[g * SD + i];
        u2_s[hh][i] = s;
    }
    __syncthreads();

    // ---- phase 3: combine u halves, outer product, 4 STG.128 ----
    float4* __restrict__ O4 = (float4*)(out + (size_t)bh * SD * SD);
    const float4 ua = ((const float4*)u2_s[0])[c4];
    const float4 ub = ((const float4*)u2_s[1])[c4];
    float4 u4;
    u4.x = ua.x + ub.x;  u4.y = ua.y + ub.y;
    u4.z = ua.z + ub.z;  u4.w = ua.w + ub.w;
    #pragma unroll
    for (int r = 0; r < KSPAN; ++r) {
        const float kq = k_r[r];
        float4 o;
        o.x = kq * u4.x;  o.y = kq * u4.y;
        o.z = kq * u4.z;  o.w = kq * u4.w;
        O4[(r * KG + grp) * C4 + c4] = o;
    }
}

extern "C" void kernel_launch(void* const* d_in, const int* in_sizes, int n_in,
                              void* d_out, int out_size)
{
    const float* Q  = (const float*)d_in[0];
    const float* K  = (const float*)d_in[1];
    const float* V  = (const float*)d_in[2];
    const float* DW = (const float*)d_in[3];
    const int* uidx = (const int*)d_in[4];
    float* out      = (float*)d_out;

    mma73_kernel<<<192, NT>>>(Q, K, V, DW, uidx, out);
}